// round 14
// baseline (speedup 1.0000x reference)
#include <cuda_runtime.h>
#include <cuda_fp16.h>
#include <math.h>
#include <stdint.h>

#define BB 2048
#define NN 256
#define MM 64
#define UU 512
#define INP 10
#define CLIPV 20.0f

#define K2 640      // 10 + 64 + 512 = 586, padded to mult of 64
#define ZN 2048
#define RWN 268
#define RWNPAD 384
#define XON 576

#define LOG2E 1.44269504088896341f

// ---------------- scratch (device globals, no allocation) ----------------
__device__ __align__(256) __half g_xcat[(size_t)BB * K2];    // [x | R0 | H0 | 0]
__device__ __align__(256) __half g_wcat_t[(size_t)ZN * K2];  // gate-interleaved [n'][k]
__device__ __align__(256) float  g_blperm[ZN];               // bl perm + bprep@Wx2 fold
__device__ __align__(256) __half g_wrw_t[(size_t)RWNPAD * UU];
__device__ __align__(256) float  g_brw[RWNPAD];
__device__ __align__(256) float  g_rw[(size_t)BB * RWN];
__device__ __align__(256) __half g_xo[(size_t)BB * XON];     // [h | R_t] half
__device__ __align__(256) __half g_wo_t[(size_t)UU * XON];

// ---------------- helpers ----------------
__device__ __forceinline__ float sigm(float x) { return 1.0f / (1.0f + expf(-x)); }
__device__ __forceinline__ float softplus(float x) {
    return (x > 20.0f) ? x : log1pf(expf(x));
}

__device__ __forceinline__ void cpasync16p(const void* smem_dst, const void* gsrc) {
    uint32_t d = (uint32_t)__cvta_generic_to_shared(smem_dst);
    asm volatile("cp.async.cg.shared.global [%0], [%1], 16;\n" :: "r"(d), "l"(gsrc));
}
__device__ __forceinline__ void cpasync_commit() {
    asm volatile("cp.async.commit_group;\n");
}
template<int NW> __device__ __forceinline__ void cpasync_wait() {
    asm volatile("cp.async.wait_group %0;\n" :: "n"(NW));
}
__device__ __forceinline__ void ldsm4(uint32_t& r0, uint32_t& r1, uint32_t& r2,
                                      uint32_t& r3, const __half* p) {
    uint32_t a = (uint32_t)__cvta_generic_to_shared(p);
    asm volatile("ldmatrix.sync.aligned.m8n8.x4.shared.b16 {%0,%1,%2,%3}, [%4];\n"
        : "=r"(r0), "=r"(r1), "=r"(r2), "=r"(r3) : "r"(a));
}
__device__ __forceinline__ void mma16816(float* d, const uint32_t* a,
                                         uint32_t b0, uint32_t b1) {
    asm volatile(
        "mma.sync.aligned.m16n8k16.row.col.f32.f16.f16.f32 "
        "{%0,%1,%2,%3}, {%4,%5,%6,%7}, {%8,%9}, {%0,%1,%2,%3};\n"
        : "+f"(d[0]), "+f"(d[1]), "+f"(d[2]), "+f"(d[3])
        : "r"(a[0]), "r"(a[1]), "r"(a[2]), "r"(a[3]), "r"(b0), "r"(b1));
}

// block reductions over 512 threads (16 warps)
__device__ __forceinline__ float blockReduceSum512(float v, volatile float* red) {
    #pragma unroll
    for (int o = 16; o; o >>= 1) v += __shfl_xor_sync(0xffffffffu, v, o);
    if ((threadIdx.x & 31) == 0) red[threadIdx.x >> 5] = v;
    __syncthreads();
    if (threadIdx.x == 0) {
        float s = 0.f;
        #pragma unroll
        for (int i = 0; i < 16; i++) s += red[i];
        red[0] = s;
    }
    __syncthreads();
    float r = red[0];
    __syncthreads();
    return r;
}
__device__ __forceinline__ float blockReduceMax512(float v, volatile float* red) {
    #pragma unroll
    for (int o = 16; o; o >>= 1) v = fmaxf(v, __shfl_xor_sync(0xffffffffu, v, o));
    if ((threadIdx.x & 31) == 0) red[threadIdx.x >> 5] = v;
    __syncthreads();
    if (threadIdx.x == 0) {
        float s = red[0];
        #pragma unroll
        for (int i = 1; i < 16; i++) s = fmaxf(s, red[i]);
        red[0] = s;
    }
    __syncthreads();
    float r = red[0];
    __syncthreads();
    return r;
}

// ================= z-GEMM (mma.sync, BK=64, 3-stage) + fused LSTM gates ====
#define GSTRIDE 72
#define GSTG (128 * GSTRIDE)
#define G_SMEM (3 * 2 * GSTG * (int)sizeof(__half))
#define GKT (K2 / 64)               // 10 chunks

__global__ __launch_bounds__(256, 2)
void hgemm_gates(const __half* __restrict__ A, const __half* __restrict__ Bt,
                 const float* __restrict__ bias, const float* __restrict__ C0,
                 __half* __restrict__ xo)
{
    constexpr int MT = 4, NT = 4, WN = 4;
    extern __shared__ __half sh[];
    __half* AsB = sh;
    __half* BsB = sh + 3 * GSTG;

    const int tid  = threadIdx.x;
    const int lane = tid & 31;
    const int warp = tid >> 5;
    const int wm = warp / WN;
    const int wn = warp % WN;
    const int brow = blockIdx.y * 128;
    const int bcol = blockIdx.x * 128;
    const int lq = lane >> 2;
    const int lr = lane & 3;

    const __half* Ablk = A + (size_t)brow * K2;
    const __half* Bblk = Bt + (size_t)bcol * K2;

    float acc[MT][NT][4];
    #pragma unroll
    for (int i = 0; i < MT; i++)
        #pragma unroll
        for (int j = 0; j < NT; j++)
            #pragma unroll
            for (int t = 0; t < 4; t++) acc[i][j][t] = 0.f;

    const int a_row = (lane & 7) + ((lane >> 3) & 1) * 8;
    const int a_ch  = (lane >> 4) * 8;
    const int b_row = ((lane >> 4) & 1) * 8 + (lane & 7);
    const int b_ch  = ((lane >> 3) & 1) * 8;

    auto loadChunk = [&](int buf, int c) {
        __half* as = AsB + buf * GSTG;
        __half* bs = BsB + buf * GSTG;
        #pragma unroll
        for (int it = 0; it < 4; it++) {
            int id = tid + it * 256;
            int row = id >> 3, c16 = id & 7;
            cpasync16p(&as[row * GSTRIDE + c16 * 8],
                       Ablk + (size_t)row * K2 + c * 64 + c16 * 8);
        }
        #pragma unroll
        for (int it = 0; it < 4; it++) {
            int id = tid + it * 256;
            int row = id >> 3, c16 = id & 7;
            cpasync16p(&bs[row * GSTRIDE + c16 * 8],
                       Bblk + (size_t)row * K2 + c * 64 + c16 * 8);
        }
        cpasync_commit();
    };

    auto computeChunk = [&](int buf) {
        const __half* as = AsB + buf * GSTG;
        const __half* bs = BsB + buf * GSTG;
        #pragma unroll
        for (int kk = 0; kk < 4; kk++) {
            uint32_t af[MT][4];
            #pragma unroll
            for (int mt = 0; mt < MT; mt++) {
                int row = wm * 64 + mt * 16 + a_row;
                ldsm4(af[mt][0], af[mt][1], af[mt][2], af[mt][3],
                      as + row * GSTRIDE + kk * 16 + a_ch);
            }
            uint32_t bf[NT][2];
            #pragma unroll
            for (int p = 0; p < NT / 2; p++) {
                int row = wn * 32 + p * 16 + b_row;
                ldsm4(bf[2 * p][0], bf[2 * p][1], bf[2 * p + 1][0], bf[2 * p + 1][1],
                      bs + row * GSTRIDE + kk * 16 + b_ch);
            }
            #pragma unroll
            for (int mt = 0; mt < MT; mt++)
                #pragma unroll
                for (int nt = 0; nt < NT; nt++)
                    mma16816(acc[mt][nt], af[mt], bf[nt][0], bf[nt][1]);
        }
    };

    loadChunk(0, 0);
    loadChunk(1, 1);
    for (int kt = 0; kt < GKT; kt++) {
        cpasync_wait<1>();
        __syncthreads();
        computeChunk(kt % 3);
        int nk = kt + 2;
        if (nk < GKT) loadChunk(nk % 3, nk);
        else cpasync_commit();
    }

    // fused LSTM epilogue (gate-interleaved columns)
    #pragma unroll
    for (int mt = 0; mt < MT; mt++) {
        #pragma unroll
        for (int hh = 0; hh < 2; hh++) {
            int row = brow + wm * 64 + mt * 16 + lq + hh * 8;
            #pragma unroll
            for (int nt = 0; nt < NT; nt++) {
                int col = bcol + wn * 32 + nt * 8 + lr * 2;
                float x0 = acc[mt][nt][hh * 2 + 0] + bias[col];
                float x1 = acc[mt][nt][hh * 2 + 1] + bias[col + 1];
                float y0 = __shfl_xor_sync(0xffffffffu, x0, 1);
                float y1 = __shfl_xor_sync(0xffffffffu, x1, 1);
                if ((lr & 1) == 0) {
                    int u = col >> 2;
                    float c = sigm(x1) * C0[(size_t)row * UU + u]
                            + sigm(x0) * tanhf(y0);
                    float h = sigm(y1) * tanhf(c);   // |h|<1, clip no-op
                    xo[(size_t)row * XON + u] = __float2half_rn(h);
                }
            }
        }
    }
}

// ---------------- fp16 mma.sync GEMM (3-stage, BK=32) ----------------
template<int BM, int BN, int WM, int WN, int MT, int NT, typename OutT>
__global__ __launch_bounds__(WM * WN * 32, 2)
void hgemm(const __half* __restrict__ A, const __half* __restrict__ Bt,
           const float* __restrict__ bias, OutT* __restrict__ C,
           int Kdim, int lda, int ldb, int ldc, int Nreal, float clipv)
{
    constexpr int THREADS = WM * WN * 32;
    extern __shared__ __half sh[];
    __half* AsB = sh;
    __half* BsB = sh + 3 * BM * 40;

    const int tid  = threadIdx.x;
    const int lane = tid & 31;
    const int warp = tid >> 5;
    const int wm = warp / WN;
    const int wn = warp % WN;
    const int brow = blockIdx.y * BM;
    const int bcol = blockIdx.x * BN;
    const int lq = lane >> 2;
    const int lr = lane & 3;

    const __half* Ablk = A + (size_t)brow * lda;
    const __half* Bblk = Bt + (size_t)bcol * ldb;

    float acc[MT][NT][4];
    #pragma unroll
    for (int i = 0; i < MT; i++)
        #pragma unroll
        for (int j = 0; j < NT; j++)
            #pragma unroll
            for (int t = 0; t < 4; t++) acc[i][j][t] = 0.f;

    const int a_row = (lane & 7) + ((lane >> 3) & 1) * 8;
    const int a_ch  = (lane >> 4) * 8;
    const int b_row = ((lane >> 4) & 1) * 8 + (lane & 7);
    const int b_ch  = ((lane >> 3) & 1) * 8;

    const int KT = Kdim / 32;

    auto loadTile = [&](int buf, int k0) {
        __half* as = AsB + buf * BM * 40;
        __half* bs = BsB + buf * BN * 40;
        #pragma unroll
        for (int i = 0; i < (BM * 4) / THREADS; i++) {
            int ch = tid + i * THREADS;
            int r = ch >> 2, co = (ch & 3) * 8;
            cpasync16p(&as[r * 40 + co], Ablk + (size_t)r * lda + k0 + co);
        }
        #pragma unroll
        for (int i = 0; i < (BN * 4) / THREADS; i++) {
            int ch = tid + i * THREADS;
            int r = ch >> 2, co = (ch & 3) * 8;
            cpasync16p(&bs[r * 40 + co], Bblk + (size_t)r * ldb + k0 + co);
        }
        cpasync_commit();
    };

    auto computeTile = [&](int buf) {
        const __half* as = AsB + buf * BM * 40;
        const __half* bs = BsB + buf * BN * 40;
        #pragma unroll
        for (int kk = 0; kk < 2; kk++) {
            uint32_t af[MT][4];
            #pragma unroll
            for (int mt = 0; mt < MT; mt++) {
                int row = wm * (MT * 16) + mt * 16 + a_row;
                ldsm4(af[mt][0], af[mt][1], af[mt][2], af[mt][3],
                      as + row * 40 + kk * 16 + a_ch);
            }
            uint32_t bf[NT][2];
            #pragma unroll
            for (int p = 0; p < NT / 2; p++) {
                int row = wn * (NT * 8) + p * 16 + b_row;
                ldsm4(bf[2 * p][0], bf[2 * p][1], bf[2 * p + 1][0], bf[2 * p + 1][1],
                      bs + row * 40 + kk * 16 + b_ch);
            }
            #pragma unroll
            for (int mt = 0; mt < MT; mt++)
                #pragma unroll
                for (int nt = 0; nt < NT; nt++)
                    mma16816(acc[mt][nt], af[mt], bf[nt][0], bf[nt][1]);
        }
    };

    loadTile(0, 0);
    if (KT > 1) loadTile(1, 32); else cpasync_commit();
    for (int kt = 0; kt < KT; kt++) {
        cpasync_wait<1>();
        __syncthreads();
        computeTile(kt % 3);
        int nk = kt + 2;
        if (nk < KT) loadTile(nk % 3, nk * 32); else cpasync_commit();
    }

    #pragma unroll
    for (int mt = 0; mt < MT; mt++) {
        #pragma unroll
        for (int hh = 0; hh < 2; hh++) {
            int row = brow + wm * (MT * 16) + mt * 16 + lq + hh * 8;
            #pragma unroll
            for (int nt = 0; nt < NT; nt++) {
                int col = bcol + wn * (NT * 8) + nt * 8 + lr * 2;
                if (col < Nreal) {
                    float v0 = acc[mt][nt][hh * 2 + 0] + bias[col];
                    float v1 = acc[mt][nt][hh * 2 + 1] + bias[col + 1];
                    if (clipv > 0.f) {
                        v0 = fminf(fmaxf(v0, -clipv), clipv);
                        v1 = fminf(fmaxf(v1, -clipv), clipv);
                    }
                    if (sizeof(OutT) == 2) {
                        *(__half2*)((__half*)C + (size_t)row * ldc + col) =
                            __halves2half2(__float2half_rn(v0), __float2half_rn(v1));
                    } else {
                        *(float2*)((float*)C + (size_t)row * ldc + col) =
                            make_float2(v0, v1);
                    }
                }
            }
        }
    }
}

// ================ merged prep kernel =================
#define PB_FOLD 32
#define PB_TRANS 1536
#define EN0 (BB * K2)
#define EN2 ZN
#define EN3 RWNPAD
#define EN4 (ZN * (K2 - 586))
#define EN5 ((RWNPAD - RWN) * UU)
#define ETOT (EN0 + EN2 + EN3 + EN4 + EN5)
#define PB_ELEM ((ETOT + 255) / 256)
#define PB_TOTAL (PB_FOLD + PB_TRANS + PB_ELEM)

__device__ __forceinline__ void doTrans(float* sp,
    const float* __restrict__ src, __half* __restrict__ dst,
    int R, int C, int ld, int kOff, int gx, int rem, bool perm)
{
    float (*tl)[33] = (float(*)[33])sp;
    int bx = rem % gx, by = rem / gx;
    int cb = bx * 32, rb = by * 32;
    int x = threadIdx.x & 31, y = threadIdx.x >> 5;
    #pragma unroll
    for (int i = 0; i < 32; i += 8) {
        int r = rb + y + i, c = cb + x;
        tl[y + i][x] = (r < R && c < C) ? src[(size_t)r * C + c] : 0.f;
    }
    __syncthreads();
    #pragma unroll
    for (int i = 0; i < 32; i += 8) {
        int c = cb + y + i, r = rb + x;
        if (c < C && r < R) {
            int cr = perm ? (4 * (c & 511) + (c >> 9)) : c;
            dst[(size_t)cr * ld + kOff + r] = __float2half(tl[x][y + i]);
        }
    }
}

__global__ __launch_bounds__(256)
void prep_all(const float* __restrict__ x_t, const float* __restrict__ H0,
              const float* __restrict__ R0, const float* __restrict__ Wprep,
              const float* __restrict__ bprep, const float* __restrict__ Wx,
              const float* __restrict__ Wh, const float* __restrict__ Wr,
              const float* __restrict__ Ww, const float* __restrict__ Wo,
              const float* __restrict__ br, const float* __restrict__ bw,
              const float* __restrict__ bl)
{
    __shared__ float sp[2 * 64 * 68];
    const int bid = blockIdx.x;
    const int tid = threadIdx.x;

    if (bid < PB_FOLD) {
        float* as = sp;
        float* bs = sp + 64 * 68;
        const int n0 = bid * 64;
        const int tx = tid & 15, ty = tid >> 4;
        float acc[4][4];
        #pragma unroll
        for (int i = 0; i < 4; i++)
            #pragma unroll
            for (int j = 0; j < 4; j++) acc[i][j] = 0.f;

        for (int k0 = 0; k0 < UU; k0 += 64) {
            #pragma unroll
            for (int l = 0; l < 16; l++) {
                int e = tid + l * 256;
                int r = e >> 6, c = e & 63;
                as[r * 68 + c] = Wprep[r * UU + k0 + c];
                bs[r * 68 + c] = Wx[(size_t)(INP + k0 + r) * ZN + n0 + c];
            }
            __syncthreads();
            #pragma unroll 8
            for (int k = 0; k < 64; k++) {
                float a4[4], b4[4];
                #pragma unroll
                for (int i = 0; i < 4; i++) a4[i] = as[(ty * 4 + i) * 68 + k];
                #pragma unroll
                for (int j = 0; j < 4; j++) b4[j] = bs[k * 68 + tx * 4 + j];
                #pragma unroll
                for (int i = 0; i < 4; i++)
                    #pragma unroll
                    for (int j = 0; j < 4; j++) acc[i][j] += a4[i] * b4[j];
            }
            __syncthreads();
        }
        #pragma unroll
        for (int j = 0; j < 4; j++) {
            int n = n0 + tx * 4 + j;
            int np = 4 * (n & 511) + (n >> 9);
            #pragma unroll
            for (int i = 0; i < 4; i++) {
                int r = ty * 4 + i;
                g_wcat_t[(size_t)np * K2 + INP + r] = __float2half(acc[i][j]);
            }
        }
        return;
    }

    if (bid < PB_FOLD + PB_TRANS) {
        int b2 = bid - PB_FOLD;
        if (b2 < 64)        doTrans(sp, Wx, g_wcat_t, 10, 2048, K2, 0, 64, b2, true);
        else if (b2 < 1088) doTrans(sp, Wh, g_wcat_t, 512, 2048, K2, 74, 64, b2 - 64, true);
        else if (b2 < 1136) doTrans(sp, Wr, g_wrw_t, 512, 70, UU, 0, 3, b2 - 1088, false);
        else if (b2 < 1248) doTrans(sp, Ww, g_wrw_t + 70 * UU, 512, 198, UU, 0, 7, b2 - 1136, false);
        else                doTrans(sp, Wo, g_wo_t, 576, 512, XON, 0, 16, b2 - 1248, false);
        return;
    }

    int idx = (bid - PB_FOLD - PB_TRANS) * 256 + tid;
    if (idx < EN0) {
        int b = idx / K2, c = idx % K2;
        float v = 0.f;
        if (c < INP)                 v = x_t[b * INP + c];
        else if (c < INP + MM)       v = R0[b * MM + (c - INP)];
        else if (c < 586)            v = H0[(size_t)b * UU + (c - 74)];
        g_xcat[idx] = __float2half(v);
        return;
    }
    idx -= EN0;
    if (idx < EN2) {
        int n = idx;
        float s = bl[n];
        #pragma unroll 8
        for (int up = 0; up < UU; up++)
            s += bprep[up] * Wx[(size_t)(INP + up) * ZN + n];
        g_blperm[4 * (n & 511) + (n >> 9)] = s;
        return;
    }
    idx -= EN2;
    if (idx < EN3) {
        float bv = 0.f;
        if (idx < 70) bv = br[idx];
        else if (idx < RWN) bv = bw[idx - 70];
        g_brw[idx] = bv;
        return;
    }
    idx -= EN3;
    if (idx < EN4) {
        const int L = K2 - 586;
        int n = idx / L, c = idx % L;
        g_wcat_t[(size_t)n * K2 + 586 + c] = __ushort_as_half(0);
        return;
    }
    idx -= EN4;
    if (idx < EN5) {
        g_wrw_t[(size_t)RWN * UU + idx] = __ushort_as_half(0);
        return;
    }
}

// ---------------- NTM addressing + memory update (512 thr, half m0 smem) ---
#define M0STRIDE 66
#define ADDR_FLOATS (256 + 64 + 512 + 256 + 256 + 64 + 64 + 16 + 8)
#define ADDR_SMEM_BYTES (NN * M0STRIDE * 2 + ADDR_FLOATS * 4)

__global__ __launch_bounds__(512)
void ntm_addr_kernel(const float* __restrict__ m0, const float* __restrict__ A0,
                     float* __restrict__ out_mt, float* __restrict__ out_Rt,
                     float* __restrict__ out_wr, float* __restrict__ out_ww,
                     __half* __restrict__ xo)
{
    extern __shared__ __align__(16) char smraw[];
    __half* m0s   = (__half*)smraw;                       // 256 x stride 66
    float* fb     = (float*)(smraw + NN * M0STRIDE * 2);
    float* mnorm  = fb;              // 256
    float* ks     = mnorm + 256;     // 64
    float* wgs    = ks + 64;         // 512 (scratch / partials)
    float* wread  = wgs + 512;       // 256
    float* wwrite = wread + 256;     // 256
    float* delv   = wwrite + 256;    // 64
    float* addv   = delv + 64;       // 64
    float* red    = addv + 64;       // 16
    float* scal   = red + 16;        // 8

    const int b = blockIdx.x;
    const int tid = threadIdx.x;
    const float4* m0g4 = (const float4*)(m0 + (size_t)b * (NN * MM));

    // load m0 -> half smem (8 iters @512 threads)
    #pragma unroll 8
    for (int e4 = tid; e4 < NN * MM / 4; e4 += 512) {
        float4 v = m0g4[e4];
        int n = e4 >> 4, m = (e4 & 15) * 4;
        __half2* p = (__half2*)&m0s[n * M0STRIDE + m];
        p[0] = __floats2half2_rn(v.x, v.y);
        p[1] = __floats2half2_rn(v.z, v.w);
    }
    __syncthreads();

    if (tid < 256) {
        float s = 0.f;
        const __half2* row = (const __half2*)&m0s[tid * M0STRIDE];
        #pragma unroll 8
        for (int m2 = 0; m2 < MM / 2; m2++) {
            float2 v = __half22float2(row[m2]);
            s += v.x * v.x + v.y * v.y;
        }
        mnorm[tid] = sqrtf(s);
    }

    const float* rwrow = g_rw + (size_t)b * RWN;

    for (int hd = 0; hd < 2; hd++) {
        const float* head = rwrow + (hd ? 70 : 0);
        if (tid < 64) ks[tid] = tanhf(head[tid]);
        if (tid == 64) {
            scal[0] = softplus(head[64]);
            scal[1] = sigm(head[65]);
            float a = head[66], bq = head[67], cq = head[68];
            float mx = fmaxf(a, fmaxf(bq, cq));
            float e0 = exp2f((a - mx) * LOG2E);
            float e1 = exp2f((bq - mx) * LOG2E);
            float e2 = exp2f((cq - mx) * LOG2E);
            float se = e0 + e1 + e2;
            scal[2] = e0 / se; scal[3] = e1 / se; scal[4] = e2 / se;
            scal[5] = softplus(head[69]);
        }
        __syncthreads();

        float kv = (tid < 64) ? ks[tid] : 0.f;
        float knorm = sqrtf(blockReduceSum512(kv * kv, red));

        float x = -1e30f;
        if (tid < 256) {
            float ip = 0.f;
            const __half2* row = (const __half2*)&m0s[tid * M0STRIDE];
            #pragma unroll 8
            for (int m2 = 0; m2 < MM / 2; m2++) {
                float2 v = __half22float2(row[m2]);
                ip += v.x * ks[2 * m2] + v.y * ks[2 * m2 + 1];
            }
            float Kv = ip / (knorm * mnorm[tid] + 1e-8f);
            x = scal[0] * Kv;
        }
        float mx = blockReduceMax512(x, red);
        float p = (tid < 256) ? exp2f((x - mx) * LOG2E) : 0.f;
        float sump = blockReduceSum512(p, red);

        float wgv = 0.f;
        if (tid < 256) {
            float wc = p / sump;
            float gg = scal[1];
            wgv = gg * wc + (1.f - gg) * A0[(size_t)hd * BB * NN + (size_t)b * NN + tid];
            wgs[tid] = wgv;
        }
        __syncthreads();

        float wsh = 0.f;
        if (tid < 256) {
            float s0 = scal[2], s1 = scal[3], s2 = scal[4], gamma = scal[5];
            float conv = s0 * wgv + s1 * wgs[(tid + 255) & 255] + s2 * wgs[(tid + 1) & 255];
            // conv >= 0; powf(conv, gamma) via exp2/log2 (limits agree at 0)
            wsh = exp2f(gamma * log2f(conv));
        }
        float ssum = blockReduceSum512(wsh, red);
        if (tid < 256) {
            float w = wsh / ssum;
            float* dst = hd ? wwrite : wread;
            dst[tid] = w;
            (hd ? out_ww : out_wr)[(size_t)b * NN + tid] = w;
        }
        __syncthreads();
    }

    if (tid < 64) {
        delv[tid] = sigm(rwrow[140 + tid]);
        addv[tid] = tanhf(rwrow[204 + tid]);
    }

    // R_t: 8 partials of 32 rows each (512 threads)
    {
        int q = tid >> 6, m = tid & 63;       // q 0..7
        float s = 0.f;
        #pragma unroll 8
        for (int n = q * 32; n < q * 32 + 32; n++)
            s += wread[n] * __half2float(m0s[n * M0STRIDE + m]);
        wgs[tid] = s;
    }
    __syncthreads();
    if (tid < 64) {
        float r = 0.f;
        #pragma unroll
        for (int j = 0; j < 8; j++) r += wgs[tid + 64 * j];
        out_Rt[(size_t)b * MM + tid] = r;
        xo[(size_t)b * XON + UU + tid] = __float2half(r);
    }

    // mt update (8 iters @512 threads); delv/addv hoisted (m loop-invariant)
    {
        int m = (tid & 15) * 4;
        float d0 = delv[m + 0], d1 = delv[m + 1], d2 = delv[m + 2], d3 = delv[m + 3];
        float a0 = addv[m + 0], a1 = addv[m + 1], a2 = addv[m + 2], a3 = addv[m + 3];
        float4* mt4 = (float4*)(out_mt + (size_t)b * (NN * MM));
        #pragma unroll 8
        for (int e4 = tid; e4 < NN * MM / 4; e4 += 512) {
            int n = e4 >> 4;
            float ww = wwrite[n];
            const __half2* p = (const __half2*)&m0s[n * M0STRIDE + m];
            float2 v01 = __half22float2(p[0]);
            float2 v23 = __half22float2(p[1]);
            float4 v;
            v.x = v01.x * (1.f - ww * d0) + ww * a0;
            v.y = v01.y * (1.f - ww * d1) + ww * a1;
            v.z = v23.x * (1.f - ww * d2) + ww * a2;
            v.w = v23.y * (1.f - ww * d3) + ww * a3;
            mt4[e4] = v;
        }
    }
}

// ---------------- launch ----------------
extern "C" void kernel_launch(void* const* d_in, const int* in_sizes, int n_in,
                              void* d_out, int out_size)
{
    const float* x_t   = (const float*)d_in[0];
    const float* H0    = (const float*)d_in[1];
    const float* C0    = (const float*)d_in[2];
    const float* m0    = (const float*)d_in[3];
    const float* R0    = (const float*)d_in[4];
    const float* A0    = (const float*)d_in[5];
    const float* Wprep = (const float*)d_in[6];
    const float* bprep = (const float*)d_in[7];
    const float* Wx    = (const float*)d_in[8];
    const float* Wh    = (const float*)d_in[9];
    const float* bl    = (const float*)d_in[10];
    const float* Wr    = (const float*)d_in[11];
    const float* br    = (const float*)d_in[12];
    const float* Ww    = (const float*)d_in[13];
    const float* bw    = (const float*)d_in[14];
    const float* Wo    = (const float*)d_in[15];
    const float* bo    = (const float*)d_in[16];

    float* out = (float*)d_out;
    float* y  = out;
    float* mt = y + (size_t)BB * UU;
    float* Rt = mt + (size_t)BB * NN * MM;
    float* wr = Rt + (size_t)BB * MM;
    float* ww = wr + (size_t)BB * NN;

    __half *xcat, *wcat_t, *wrw_t, *xo, *wo_t;
    float *blperm, *brw, *rw;
    cudaGetSymbolAddress((void**)&xcat, g_xcat);
    cudaGetSymbolAddress((void**)&wcat_t, g_wcat_t);
    cudaGetSymbolAddress((void**)&blperm, g_blperm);
    cudaGetSymbolAddress((void**)&wrw_t, g_wrw_t);
    cudaGetSymbolAddress((void**)&brw, g_brw);
    cudaGetSymbolAddress((void**)&rw, g_rw);
    cudaGetSymbolAddress((void**)&xo, g_xo);
    cudaGetSymbolAddress((void**)&wo_t, g_wo_t);

    const int SM_64 = 3 * (64 + 64) * 40 * (int)sizeof(__half);
    cudaFuncSetAttribute(hgemm_gates,
        cudaFuncAttributeMaxDynamicSharedMemorySize, G_SMEM);
    cudaFuncSetAttribute(hgemm<64, 64, 2, 2, 2, 4, float>,
        cudaFuncAttributeMaxDynamicSharedMemorySize, SM_64);

    // 1) all prep (Wfold GEMM + transposes + elementwise + bias fold)
    prep_all<<<PB_TOTAL, 256>>>(x_t, H0, R0, Wprep, bprep, Wx, Wh,
                                Wr, Ww, Wo, br, bw, bl);

    // 2) z GEMM (K=640) + fused LSTM gates -> h into xo cols [0,512)
    hgemm_gates<<<dim3(ZN / 128, BB / 128), 256, G_SMEM>>>(
        xcat, wcat_t, blperm, C0, xo);

    // 3) [r_out | w_out] = h @ [Wr | Ww]
    hgemm<64, 64, 2, 2, 2, 4, float><<<dim3(RWNPAD / 64, BB / 64), 128, SM_64>>>(
        xo, wrw_t, brw, rw, UU, XON, UU, RWN, RWN, 0.f);

    // 4) addressing + memory update (512 threads, ~full occupancy)
    {
        cudaFuncSetAttribute(ntm_addr_kernel,
                             cudaFuncAttributeMaxDynamicSharedMemorySize,
                             ADDR_SMEM_BYTES);
        ntm_addr_kernel<<<BB, 512, ADDR_SMEM_BYTES>>>(m0, A0, mt, Rt, wr, ww, xo);
    }

    // 5) y = [h | R_t] @ Wo + bo, clipped
    hgemm<64, 64, 2, 2, 2, 4, float><<<dim3(UU / 64, BB / 64), 128, SM_64>>>(
        xo, wo_t, bo, y, XON, XON, XON, UU, UU, CLIPV);
}

// round 16
// speedup vs baseline: 1.4871x; 1.4871x over previous
#include <cuda_runtime.h>
#include <cuda_fp16.h>
#include <math.h>
#include <stdint.h>

#define BB 2048
#define NN 256
#define MM 64
#define UU 512
#define INP 10
#define CLIPV 20.0f

#define K2 640      // 10 + 64 + 512 = 586, padded to mult of 64
#define ZN 2048
#define RWN 268
#define RWNPAD 384
#define XON 576

#define LOG2E 1.44269504088896341f

// ---------------- scratch (device globals, no allocation) ----------------
__device__ __align__(256) __half g_xcat[(size_t)BB * K2];    // [x | R0 | H0 | 0]
__device__ __align__(256) __half g_wcat_t[(size_t)ZN * K2];  // gate-interleaved [n'][k]
__device__ __align__(256) float  g_blperm[ZN];               // bl perm + bprep@Wx2 fold
__device__ __align__(256) __half g_wrw_t[(size_t)RWNPAD * UU];
__device__ __align__(256) float  g_brw[RWNPAD];
__device__ __align__(256) float  g_rw[(size_t)BB * RWN];
__device__ __align__(256) __half g_xo[(size_t)BB * XON];     // [h | R_t] half
__device__ __align__(256) __half g_wo_t[(size_t)UU * XON];

// ---------------- helpers ----------------
__device__ __forceinline__ float sigm(float x) { return 1.0f / (1.0f + expf(-x)); }
__device__ __forceinline__ float softplus(float x) {
    return (x > 20.0f) ? x : log1pf(expf(x));
}

__device__ __forceinline__ void cpasync16p(const void* smem_dst, const void* gsrc) {
    uint32_t d = (uint32_t)__cvta_generic_to_shared(smem_dst);
    asm volatile("cp.async.cg.shared.global [%0], [%1], 16;\n" :: "r"(d), "l"(gsrc));
}
__device__ __forceinline__ void cpasync_commit() {
    asm volatile("cp.async.commit_group;\n");
}
template<int NW> __device__ __forceinline__ void cpasync_wait() {
    asm volatile("cp.async.wait_group %0;\n" :: "n"(NW));
}
__device__ __forceinline__ void ldsm4(uint32_t& r0, uint32_t& r1, uint32_t& r2,
                                      uint32_t& r3, const __half* p) {
    uint32_t a = (uint32_t)__cvta_generic_to_shared(p);
    asm volatile("ldmatrix.sync.aligned.m8n8.x4.shared.b16 {%0,%1,%2,%3}, [%4];\n"
        : "=r"(r0), "=r"(r1), "=r"(r2), "=r"(r3) : "r"(a));
}
__device__ __forceinline__ void mma16816(float* d, const uint32_t* a,
                                         uint32_t b0, uint32_t b1) {
    asm volatile(
        "mma.sync.aligned.m16n8k16.row.col.f32.f16.f16.f32 "
        "{%0,%1,%2,%3}, {%4,%5,%6,%7}, {%8,%9}, {%0,%1,%2,%3};\n"
        : "+f"(d[0]), "+f"(d[1]), "+f"(d[2]), "+f"(d[3])
        : "r"(a[0]), "r"(a[1]), "r"(a[2]), "r"(a[3]), "r"(b0), "r"(b1));
}

__device__ __forceinline__ float blockReduceSum(float v, volatile float* red) {
    #pragma unroll
    for (int o = 16; o; o >>= 1) v += __shfl_xor_sync(0xffffffffu, v, o);
    if ((threadIdx.x & 31) == 0) red[threadIdx.x >> 5] = v;
    __syncthreads();
    if (threadIdx.x == 0) {
        float s = 0.f;
        #pragma unroll
        for (int i = 0; i < 8; i++) s += red[i];
        red[0] = s;
    }
    __syncthreads();
    float r = red[0];
    __syncthreads();
    return r;
}
__device__ __forceinline__ float blockReduceMax(float v, volatile float* red) {
    #pragma unroll
    for (int o = 16; o; o >>= 1) v = fmaxf(v, __shfl_xor_sync(0xffffffffu, v, o));
    if ((threadIdx.x & 31) == 0) red[threadIdx.x >> 5] = v;
    __syncthreads();
    if (threadIdx.x == 0) {
        float s = red[0];
        #pragma unroll
        for (int i = 1; i < 8; i++) s = fmaxf(s, red[i]);
        red[0] = s;
    }
    __syncthreads();
    float r = red[0];
    __syncthreads();
    return r;
}

// ================= z-GEMM (mma.sync, BK=64, 3-stage) + fused LSTM gates ====
#define GSTRIDE 72
#define GSTG (128 * GSTRIDE)
#define G_SMEM (3 * 2 * GSTG * (int)sizeof(__half))
#define GKT (K2 / 64)               // 10 chunks

__global__ __launch_bounds__(256, 2)
void hgemm_gates(const __half* __restrict__ A, const __half* __restrict__ Bt,
                 const float* __restrict__ bias, const float* __restrict__ C0,
                 __half* __restrict__ xo)
{
    constexpr int MT = 4, NT = 4, WN = 4;
    extern __shared__ __half sh[];
    __half* AsB = sh;
    __half* BsB = sh + 3 * GSTG;

    const int tid  = threadIdx.x;
    const int lane = tid & 31;
    const int warp = tid >> 5;
    const int wm = warp / WN;
    const int wn = warp % WN;
    const int brow = blockIdx.y * 128;
    const int bcol = blockIdx.x * 128;
    const int lq = lane >> 2;
    const int lr = lane & 3;

    const __half* Ablk = A + (size_t)brow * K2;
    const __half* Bblk = Bt + (size_t)bcol * K2;

    float acc[MT][NT][4];
    #pragma unroll
    for (int i = 0; i < MT; i++)
        #pragma unroll
        for (int j = 0; j < NT; j++)
            #pragma unroll
            for (int t = 0; t < 4; t++) acc[i][j][t] = 0.f;

    const int a_row = (lane & 7) + ((lane >> 3) & 1) * 8;
    const int a_ch  = (lane >> 4) * 8;
    const int b_row = ((lane >> 4) & 1) * 8 + (lane & 7);
    const int b_ch  = ((lane >> 3) & 1) * 8;

    auto loadChunk = [&](int buf, int c) {
        __half* as = AsB + buf * GSTG;
        __half* bs = BsB + buf * GSTG;
        #pragma unroll
        for (int it = 0; it < 4; it++) {
            int id = tid + it * 256;
            int row = id >> 3, c16 = id & 7;
            cpasync16p(&as[row * GSTRIDE + c16 * 8],
                       Ablk + (size_t)row * K2 + c * 64 + c16 * 8);
        }
        #pragma unroll
        for (int it = 0; it < 4; it++) {
            int id = tid + it * 256;
            int row = id >> 3, c16 = id & 7;
            cpasync16p(&bs[row * GSTRIDE + c16 * 8],
                       Bblk + (size_t)row * K2 + c * 64 + c16 * 8);
        }
        cpasync_commit();
    };

    auto computeChunk = [&](int buf) {
        const __half* as = AsB + buf * GSTG;
        const __half* bs = BsB + buf * GSTG;
        #pragma unroll
        for (int kk = 0; kk < 4; kk++) {
            uint32_t af[MT][4];
            #pragma unroll
            for (int mt = 0; mt < MT; mt++) {
                int row = wm * 64 + mt * 16 + a_row;
                ldsm4(af[mt][0], af[mt][1], af[mt][2], af[mt][3],
                      as + row * GSTRIDE + kk * 16 + a_ch);
            }
            uint32_t bf[NT][2];
            #pragma unroll
            for (int p = 0; p < NT / 2; p++) {
                int row = wn * 32 + p * 16 + b_row;
                ldsm4(bf[2 * p][0], bf[2 * p][1], bf[2 * p + 1][0], bf[2 * p + 1][1],
                      bs + row * GSTRIDE + kk * 16 + b_ch);
            }
            #pragma unroll
            for (int mt = 0; mt < MT; mt++)
                #pragma unroll
                for (int nt = 0; nt < NT; nt++)
                    mma16816(acc[mt][nt], af[mt], bf[nt][0], bf[nt][1]);
        }
    };

    loadChunk(0, 0);
    loadChunk(1, 1);
    for (int kt = 0; kt < GKT; kt++) {
        cpasync_wait<1>();
        __syncthreads();
        computeChunk(kt % 3);
        int nk = kt + 2;
        if (nk < GKT) loadChunk(nk % 3, nk);
        else cpasync_commit();
    }

    // fused LSTM epilogue (gate-interleaved columns)
    #pragma unroll
    for (int mt = 0; mt < MT; mt++) {
        #pragma unroll
        for (int hh = 0; hh < 2; hh++) {
            int row = brow + wm * 64 + mt * 16 + lq + hh * 8;
            #pragma unroll
            for (int nt = 0; nt < NT; nt++) {
                int col = bcol + wn * 32 + nt * 8 + lr * 2;
                float x0 = acc[mt][nt][hh * 2 + 0] + bias[col];
                float x1 = acc[mt][nt][hh * 2 + 1] + bias[col + 1];
                float y0 = __shfl_xor_sync(0xffffffffu, x0, 1);
                float y1 = __shfl_xor_sync(0xffffffffu, x1, 1);
                if ((lr & 1) == 0) {
                    int u = col >> 2;
                    float c = sigm(x1) * C0[(size_t)row * UU + u]
                            + sigm(x0) * tanhf(y0);
                    float h = sigm(y1) * tanhf(c);   // |h|<1, clip no-op
                    xo[(size_t)row * XON + u] = __float2half_rn(h);
                }
            }
        }
    }
}

// ---------------- fp16 mma.sync GEMM (3-stage, BK=32) ----------------
template<int BM, int BN, int WM, int WN, int MT, int NT, typename OutT>
__global__ __launch_bounds__(WM * WN * 32, 2)
void hgemm(const __half* __restrict__ A, const __half* __restrict__ Bt,
           const float* __restrict__ bias, OutT* __restrict__ C,
           int Kdim, int lda, int ldb, int ldc, int Nreal, float clipv)
{
    constexpr int THREADS = WM * WN * 32;
    extern __shared__ __half sh[];
    __half* AsB = sh;
    __half* BsB = sh + 3 * BM * 40;

    const int tid  = threadIdx.x;
    const int lane = tid & 31;
    const int warp = tid >> 5;
    const int wm = warp / WN;
    const int wn = warp % WN;
    const int brow = blockIdx.y * BM;
    const int bcol = blockIdx.x * BN;
    const int lq = lane >> 2;
    const int lr = lane & 3;

    const __half* Ablk = A + (size_t)brow * lda;
    const __half* Bblk = Bt + (size_t)bcol * ldb;

    float acc[MT][NT][4];
    #pragma unroll
    for (int i = 0; i < MT; i++)
        #pragma unroll
        for (int j = 0; j < NT; j++)
            #pragma unroll
            for (int t = 0; t < 4; t++) acc[i][j][t] = 0.f;

    const int a_row = (lane & 7) + ((lane >> 3) & 1) * 8;
    const int a_ch  = (lane >> 4) * 8;
    const int b_row = ((lane >> 4) & 1) * 8 + (lane & 7);
    const int b_ch  = ((lane >> 3) & 1) * 8;

    const int KT = Kdim / 32;

    auto loadTile = [&](int buf, int k0) {
        __half* as = AsB + buf * BM * 40;
        __half* bs = BsB + buf * BN * 40;
        #pragma unroll
        for (int i = 0; i < (BM * 4) / THREADS; i++) {
            int ch = tid + i * THREADS;
            int r = ch >> 2, co = (ch & 3) * 8;
            cpasync16p(&as[r * 40 + co], Ablk + (size_t)r * lda + k0 + co);
        }
        #pragma unroll
        for (int i = 0; i < (BN * 4) / THREADS; i++) {
            int ch = tid + i * THREADS;
            int r = ch >> 2, co = (ch & 3) * 8;
            cpasync16p(&bs[r * 40 + co], Bblk + (size_t)r * ldb + k0 + co);
        }
        cpasync_commit();
    };

    auto computeTile = [&](int buf) {
        const __half* as = AsB + buf * BM * 40;
        const __half* bs = BsB + buf * BN * 40;
        #pragma unroll
        for (int kk = 0; kk < 2; kk++) {
            uint32_t af[MT][4];
            #pragma unroll
            for (int mt = 0; mt < MT; mt++) {
                int row = wm * (MT * 16) + mt * 16 + a_row;
                ldsm4(af[mt][0], af[mt][1], af[mt][2], af[mt][3],
                      as + row * 40 + kk * 16 + a_ch);
            }
            uint32_t bf[NT][2];
            #pragma unroll
            for (int p = 0; p < NT / 2; p++) {
                int row = wn * (NT * 8) + p * 16 + b_row;
                ldsm4(bf[2 * p][0], bf[2 * p][1], bf[2 * p + 1][0], bf[2 * p + 1][1],
                      bs + row * 40 + kk * 16 + b_ch);
            }
            #pragma unroll
            for (int mt = 0; mt < MT; mt++)
                #pragma unroll
                for (int nt = 0; nt < NT; nt++)
                    mma16816(acc[mt][nt], af[mt], bf[nt][0], bf[nt][1]);
        }
    };

    loadTile(0, 0);
    if (KT > 1) loadTile(1, 32); else cpasync_commit();
    for (int kt = 0; kt < KT; kt++) {
        cpasync_wait<1>();
        __syncthreads();
        computeTile(kt % 3);
        int nk = kt + 2;
        if (nk < KT) loadTile(nk % 3, nk * 32); else cpasync_commit();
    }

    #pragma unroll
    for (int mt = 0; mt < MT; mt++) {
        #pragma unroll
        for (int hh = 0; hh < 2; hh++) {
            int row = brow + wm * (MT * 16) + mt * 16 + lq + hh * 8;
            #pragma unroll
            for (int nt = 0; nt < NT; nt++) {
                int col = bcol + wn * (NT * 8) + nt * 8 + lr * 2;
                if (col < Nreal) {
                    float v0 = acc[mt][nt][hh * 2 + 0] + bias[col];
                    float v1 = acc[mt][nt][hh * 2 + 1] + bias[col + 1];
                    if (clipv > 0.f) {
                        v0 = fminf(fmaxf(v0, -clipv), clipv);
                        v1 = fminf(fmaxf(v1, -clipv), clipv);
                    }
                    if (sizeof(OutT) == 2) {
                        *(__half2*)((__half*)C + (size_t)row * ldc + col) =
                            __halves2half2(__float2half_rn(v0), __float2half_rn(v1));
                    } else {
                        *(float2*)((float*)C + (size_t)row * ldc + col) =
                            make_float2(v0, v1);
                    }
                }
            }
        }
    }
}

// ================ merged prep kernel =================
#define PB_FOLD 32
#define PB_TRANS 1536
#define EN0 (BB * K2)
#define EN2 ZN
#define EN3 RWNPAD
#define EN4 (ZN * (K2 - 586))
#define EN5 ((RWNPAD - RWN) * UU)
#define ETOT (EN0 + EN2 + EN3 + EN4 + EN5)
#define PB_ELEM ((ETOT + 255) / 256)
#define PB_TOTAL (PB_FOLD + PB_TRANS + PB_ELEM)

__device__ __forceinline__ void doTrans(float* sp,
    const float* __restrict__ src, __half* __restrict__ dst,
    int R, int C, int ld, int kOff, int gx, int rem, bool perm)
{
    float (*tl)[33] = (float(*)[33])sp;
    int bx = rem % gx, by = rem / gx;
    int cb = bx * 32, rb = by * 32;
    int x = threadIdx.x & 31, y = threadIdx.x >> 5;
    #pragma unroll
    for (int i = 0; i < 32; i += 8) {
        int r = rb + y + i, c = cb + x;
        tl[y + i][x] = (r < R && c < C) ? src[(size_t)r * C + c] : 0.f;
    }
    __syncthreads();
    #pragma unroll
    for (int i = 0; i < 32; i += 8) {
        int c = cb + y + i, r = rb + x;
        if (c < C && r < R) {
            int cr = perm ? (4 * (c & 511) + (c >> 9)) : c;
            dst[(size_t)cr * ld + kOff + r] = __float2half(tl[x][y + i]);
        }
    }
}

__global__ __launch_bounds__(256)
void prep_all(const float* __restrict__ x_t, const float* __restrict__ H0,
              const float* __restrict__ R0, const float* __restrict__ Wprep,
              const float* __restrict__ bprep, const float* __restrict__ Wx,
              const float* __restrict__ Wh, const float* __restrict__ Wr,
              const float* __restrict__ Ww, const float* __restrict__ Wo,
              const float* __restrict__ br, const float* __restrict__ bw,
              const float* __restrict__ bl)
{
    __shared__ float sp[2 * 64 * 68];
    const int bid = blockIdx.x;
    const int tid = threadIdx.x;

    if (bid < PB_FOLD) {
        float* as = sp;
        float* bs = sp + 64 * 68;
        const int n0 = bid * 64;
        const int tx = tid & 15, ty = tid >> 4;
        float acc[4][4];
        #pragma unroll
        for (int i = 0; i < 4; i++)
            #pragma unroll
            for (int j = 0; j < 4; j++) acc[i][j] = 0.f;

        for (int k0 = 0; k0 < UU; k0 += 64) {
            #pragma unroll
            for (int l = 0; l < 16; l++) {
                int e = tid + l * 256;
                int r = e >> 6, c = e & 63;
                as[r * 68 + c] = Wprep[r * UU + k0 + c];
                bs[r * 68 + c] = Wx[(size_t)(INP + k0 + r) * ZN + n0 + c];
            }
            __syncthreads();
            #pragma unroll 8
            for (int k = 0; k < 64; k++) {
                float a4[4], b4[4];
                #pragma unroll
                for (int i = 0; i < 4; i++) a4[i] = as[(ty * 4 + i) * 68 + k];
                #pragma unroll
                for (int j = 0; j < 4; j++) b4[j] = bs[k * 68 + tx * 4 + j];
                #pragma unroll
                for (int i = 0; i < 4; i++)
                    #pragma unroll
                    for (int j = 0; j < 4; j++) acc[i][j] += a4[i] * b4[j];
            }
            __syncthreads();
        }
        #pragma unroll
        for (int j = 0; j < 4; j++) {
            int n = n0 + tx * 4 + j;
            int np = 4 * (n & 511) + (n >> 9);
            #pragma unroll
            for (int i = 0; i < 4; i++) {
                int r = ty * 4 + i;
                g_wcat_t[(size_t)np * K2 + INP + r] = __float2half(acc[i][j]);
            }
        }
        return;
    }

    if (bid < PB_FOLD + PB_TRANS) {
        int b2 = bid - PB_FOLD;
        if (b2 < 64)        doTrans(sp, Wx, g_wcat_t, 10, 2048, K2, 0, 64, b2, true);
        else if (b2 < 1088) doTrans(sp, Wh, g_wcat_t, 512, 2048, K2, 74, 64, b2 - 64, true);
        else if (b2 < 1136) doTrans(sp, Wr, g_wrw_t, 512, 70, UU, 0, 3, b2 - 1088, false);
        else if (b2 < 1248) doTrans(sp, Ww, g_wrw_t + 70 * UU, 512, 198, UU, 0, 7, b2 - 1136, false);
        else                doTrans(sp, Wo, g_wo_t, 576, 512, XON, 0, 16, b2 - 1248, false);
        return;
    }

    int idx = (bid - PB_FOLD - PB_TRANS) * 256 + tid;
    if (idx < EN0) {
        int b = idx / K2, c = idx % K2;
        float v = 0.f;
        if (c < INP)                 v = x_t[b * INP + c];
        else if (c < INP + MM)       v = R0[b * MM + (c - INP)];
        else if (c < 586)            v = H0[(size_t)b * UU + (c - 74)];
        g_xcat[idx] = __float2half(v);
        return;
    }
    idx -= EN0;
    if (idx < EN2) {
        int n = idx;
        float s = bl[n];
        #pragma unroll 8
        for (int up = 0; up < UU; up++)
            s += bprep[up] * Wx[(size_t)(INP + up) * ZN + n];
        g_blperm[4 * (n & 511) + (n >> 9)] = s;
        return;
    }
    idx -= EN2;
    if (idx < EN3) {
        float bv = 0.f;
        if (idx < 70) bv = br[idx];
        else if (idx < RWN) bv = bw[idx - 70];
        g_brw[idx] = bv;
        return;
    }
    idx -= EN3;
    if (idx < EN4) {
        const int L = K2 - 586;
        int n = idx / L, c = idx % L;
        g_wcat_t[(size_t)n * K2 + 586 + c] = __ushort_as_half(0);
        return;
    }
    idx -= EN4;
    if (idx < EN5) {
        g_wrw_t[(size_t)RWN * UU + idx] = __ushort_as_half(0);
        return;
    }
}

// ---------------- NTM addressing + memory update (256 thr, half m0 smem) ---
#define M0STRIDE 66
#define ADDR_SMEM_BYTES (NN * M0STRIDE * 2 + (256 + 64 + 256 + 256 + 256 + 64 + 64 + 32 + 8) * 4)

__global__ __launch_bounds__(256)
void ntm_addr_kernel(const float* __restrict__ m0, const float* __restrict__ A0,
                     float* __restrict__ out_mt, float* __restrict__ out_Rt,
                     float* __restrict__ out_wr, float* __restrict__ out_ww,
                     __half* __restrict__ xo)
{
    extern __shared__ __align__(16) char smraw[];
    __half* m0s   = (__half*)smraw;                       // 256 x stride 66
    float* fb     = (float*)(smraw + NN * M0STRIDE * 2);
    float* mnorm  = fb;
    float* ks     = mnorm + 256;
    float* wgs    = ks + 64;
    float* wread  = wgs + 256;
    float* wwrite = wread + 256;
    float* delv   = wwrite + 256;
    float* addv   = delv + 64;
    float* red    = addv + 64;
    float* scal   = red + 32;

    const int b = blockIdx.x;
    const int tid = threadIdx.x;
    const float4* m0g4 = (const float4*)(m0 + (size_t)b * (NN * MM));

    #pragma unroll 4
    for (int e4 = tid; e4 < NN * MM / 4; e4 += 256) {
        float4 v = m0g4[e4];
        int n = e4 >> 4, m = (e4 & 15) * 4;
        __half2* p = (__half2*)&m0s[n * M0STRIDE + m];
        p[0] = __floats2half2_rn(v.x, v.y);
        p[1] = __floats2half2_rn(v.z, v.w);
    }
    __syncthreads();

    {
        float s = 0.f;
        const __half2* row = (const __half2*)&m0s[tid * M0STRIDE];
        #pragma unroll 8
        for (int m2 = 0; m2 < MM / 2; m2++) {
            float2 v = __half22float2(row[m2]);
            s += v.x * v.x + v.y * v.y;
        }
        mnorm[tid] = sqrtf(s);
    }

    const float* rwrow = g_rw + (size_t)b * RWN;

    for (int hd = 0; hd < 2; hd++) {
        const float* head = rwrow + (hd ? 70 : 0);
        if (tid < 64) ks[tid] = tanhf(head[tid]);
        if (tid == 64) {
            scal[0] = softplus(head[64]);
            scal[1] = sigm(head[65]);
            float a = head[66], bq = head[67], cq = head[68];
            float mx = fmaxf(a, fmaxf(bq, cq));
            float e0 = exp2f((a - mx) * LOG2E);
            float e1 = exp2f((bq - mx) * LOG2E);
            float e2 = exp2f((cq - mx) * LOG2E);
            float se = e0 + e1 + e2;
            scal[2] = e0 / se; scal[3] = e1 / se; scal[4] = e2 / se;
            scal[5] = softplus(head[69]);
        }
        __syncthreads();

        float kv = (tid < 64) ? ks[tid] : 0.f;
        float knorm = sqrtf(blockReduceSum(kv * kv, red));

        float ip = 0.f;
        {
            const __half2* row = (const __half2*)&m0s[tid * M0STRIDE];
            #pragma unroll 8
            for (int m2 = 0; m2 < MM / 2; m2++) {
                float2 v = __half22float2(row[m2]);
                ip += v.x * ks[2 * m2] + v.y * ks[2 * m2 + 1];
            }
        }
        float Kv = ip / (knorm * mnorm[tid] + 1e-8f);
        float x = scal[0] * Kv;
        float mx = blockReduceMax(x, red);
        float p = exp2f((x - mx) * LOG2E);
        float sump = blockReduceSum(p, red);
        float wc = p / sump;

        float gg = scal[1];
        float wgv = gg * wc + (1.f - gg) * A0[(size_t)hd * BB * NN + (size_t)b * NN + tid];
        wgs[tid] = wgv;
        __syncthreads();

        float s0 = scal[2], s1 = scal[3], s2 = scal[4], gamma = scal[5];
        float conv = s0 * wgv + s1 * wgs[(tid + 255) & 255] + s2 * wgs[(tid + 1) & 255];
        // conv >= 0; powf(conv, gamma) via exp2/log2 (limits agree at 0)
        float wsh = exp2f(gamma * log2f(conv));
        float ssum = blockReduceSum(wsh, red);
        float w = wsh / ssum;

        float* dst = hd ? wwrite : wread;
        dst[tid] = w;
        (hd ? out_ww : out_wr)[(size_t)b * NN + tid] = w;
        __syncthreads();
    }

    if (tid < 64) {
        delv[tid] = sigm(rwrow[140 + tid]);
        addv[tid] = tanhf(rwrow[204 + tid]);
    }

    {
        int q = tid >> 6, m = tid & 63;
        float s = 0.f;
        #pragma unroll 8
        for (int n = q * 64; n < q * 64 + 64; n++)
            s += wread[n] * __half2float(m0s[n * M0STRIDE + m]);
        wgs[tid] = s;
    }
    __syncthreads();
    if (tid < 64) {
        float r = wgs[tid] + wgs[64 + tid] + wgs[128 + tid] + wgs[192 + tid];
        out_Rt[(size_t)b * MM + tid] = r;
        xo[(size_t)b * XON + UU + tid] = __float2half(r);
    }

    // mt update; delv/addv hoisted (m loop-invariant per thread)
    {
        int m = (tid & 15) * 4;
        float d0 = delv[m + 0], d1 = delv[m + 1], d2 = delv[m + 2], d3 = delv[m + 3];
        float a0 = addv[m + 0], a1 = addv[m + 1], a2 = addv[m + 2], a3 = addv[m + 3];
        float4* mt4 = (float4*)(out_mt + (size_t)b * (NN * MM));
        #pragma unroll 4
        for (int e4 = tid; e4 < NN * MM / 4; e4 += 256) {
            int n = e4 >> 4;
            float ww = wwrite[n];
            const __half2* p = (const __half2*)&m0s[n * M0STRIDE + m];
            float2 v01 = __half22float2(p[0]);
            float2 v23 = __half22float2(p[1]);
            float4 v;
            v.x = v01.x * (1.f - ww * d0) + ww * a0;
            v.y = v01.y * (1.f - ww * d1) + ww * a1;
            v.z = v23.x * (1.f - ww * d2) + ww * a2;
            v.w = v23.y * (1.f - ww * d3) + ww * a3;
            mt4[e4] = v;
        }
    }
}

// ---------------- launch ----------------
extern "C" void kernel_launch(void* const* d_in, const int* in_sizes, int n_in,
                              void* d_out, int out_size)
{
    const float* x_t   = (const float*)d_in[0];
    const float* H0    = (const float*)d_in[1];
    const float* C0    = (const float*)d_in[2];
    const float* m0    = (const float*)d_in[3];
    const float* R0    = (const float*)d_in[4];
    const float* A0    = (const float*)d_in[5];
    const float* Wprep = (const float*)d_in[6];
    const float* bprep = (const float*)d_in[7];
    const float* Wx    = (const float*)d_in[8];
    const float* Wh    = (const float*)d_in[9];
    const float* bl    = (const float*)d_in[10];
    const float* Wr    = (const float*)d_in[11];
    const float* br    = (const float*)d_in[12];
    const float* Ww    = (const float*)d_in[13];
    const float* bw    = (const float*)d_in[14];
    const float* Wo    = (const float*)d_in[15];
    const float* bo    = (const float*)d_in[16];

    float* out = (float*)d_out;
    float* y  = out;
    float* mt = y + (size_t)BB * UU;
    float* Rt = mt + (size_t)BB * NN * MM;
    float* wr = Rt + (size_t)BB * MM;
    float* ww = wr + (size_t)BB * NN;

    __half *xcat, *wcat_t, *wrw_t, *xo, *wo_t;
    float *blperm, *brw, *rw;
    cudaGetSymbolAddress((void**)&xcat, g_xcat);
    cudaGetSymbolAddress((void**)&wcat_t, g_wcat_t);
    cudaGetSymbolAddress((void**)&blperm, g_blperm);
    cudaGetSymbolAddress((void**)&wrw_t, g_wrw_t);
    cudaGetSymbolAddress((void**)&brw, g_brw);
    cudaGetSymbolAddress((void**)&rw, g_rw);
    cudaGetSymbolAddress((void**)&xo, g_xo);
    cudaGetSymbolAddress((void**)&wo_t, g_wo_t);

    const int SM_64 = 3 * (64 + 64) * 40 * (int)sizeof(__half);
    cudaFuncSetAttribute(hgemm_gates,
        cudaFuncAttributeMaxDynamicSharedMemorySize, G_SMEM);
    cudaFuncSetAttribute(hgemm<64, 64, 2, 2, 2, 4, float>,
        cudaFuncAttributeMaxDynamicSharedMemorySize, SM_64);

    // 1) all prep (Wfold GEMM + transposes + elementwise + bias fold)
    prep_all<<<PB_TOTAL, 256>>>(x_t, H0, R0, Wprep, bprep, Wx, Wh,
                                Wr, Ww, Wo, br, bw, bl);

    // 2) z GEMM (K=640) + fused LSTM gates -> h into xo cols [0,512)
    hgemm_gates<<<dim3(ZN / 128, BB / 128), 256, G_SMEM>>>(
        xcat, wcat_t, blperm, C0, xo);

    // 3) [r_out | w_out] = h @ [Wr | Ww]
    hgemm<64, 64, 2, 2, 2, 4, float><<<dim3(RWNPAD / 64, BB / 64), 128, SM_64>>>(
        xo, wrw_t, brw, rw, UU, XON, UU, RWN, RWN, 0.f);

    // 4) addressing + memory update (256 threads, 5 CTAs/SM)
    {
        cudaFuncSetAttribute(ntm_addr_kernel,
                             cudaFuncAttributeMaxDynamicSharedMemorySize,
                             ADDR_SMEM_BYTES);
        ntm_addr_kernel<<<BB, 256, ADDR_SMEM_BYTES>>>(m0, A0, mt, Rt, wr, ww, xo);
    }

    // 5) y = [h | R_t] @ Wo + bo, clipped
    hgemm<64, 64, 2, 2, 2, 4, float><<<dim3(UU / 64, BB / 64), 128, SM_64>>>(
        xo, wo_t, bo, y, XON, XON, XON, UU, UU, CLIPV);
}